// round 4
// baseline (speedup 1.0000x reference)
#include <cuda_runtime.h>
#include <math.h>

// Problem constants
#define SQ    2048      // sequence length
#define HID   2048      // hidden
#define NHEAD 16
#define HDIM  128
#define MR    4096      // B*S rows

typedef unsigned long long ull;

// ---------------- scratch (static device arrays; no allocation allowed) ----------
__device__ float g_q [MR * HID];
__device__ float g_k [MR * HID];
__device__ float g_v [MR * HID];
__device__ float g_ao[MR * HID];
__device__ float g_bm[SQ];
__device__ float g_attn[134217728];   // 2*16*2048*2048 fallback if attn not in d_out

// ---------------- f32x2 helpers (Blackwell packed fp32 FMA) ----------------------
__device__ __forceinline__ ull dup2(float a) {
    ull r; asm("mov.b64 %0, {%1, %1};" : "=l"(r) : "f"(a)); return r;
}
__device__ __forceinline__ void fma2(ull& d, ull a, ull b) {
    asm("fma.rn.f32x2 %0, %1, %2, %0;" : "+l"(d) : "l"(a), "l"(b));
}
__device__ __forceinline__ float2 unpk(ull v) {
    float lo, hi; asm("mov.b64 {%0, %1}, %2;" : "=f"(lo), "=f"(hi) : "l"(v));
    return make_float2(lo, hi);
}

// =================================================================================
// NT GEMM: C[m,n] = scale * sum_k A[m,k] * B[n,k]
// 128x128 tile, BK=16, 256 threads, 8x8 per thread with f32x2 accumulators.
// Batched via blockIdx.z with (outer, inner) stride decomposition.
// causal!=0: skip tiles entirely above the diagonal (scores GEMM).
// =================================================================================
__global__ void __launch_bounds__(256, 2) gemm_nt_kernel(
    const float* __restrict__ A, const float* __restrict__ B, float* __restrict__ C,
    int K, int lda, int ldb, int ldc,
    long long aSb, long long aSh, long long bSb, long long bSh,
    long long cSb, long long cSh, int nInner, float scale, int causal)
{
    int z  = blockIdx.z;
    int bb = z / nInner, hh = z - bb * nInner;
    A += bb * aSb + hh * aSh;
    B += bb * bSb + hh * bSh;
    C += bb * cSb + hh * cSh;

    const int rowBase = blockIdx.y * 128;
    const int colBase = blockIdx.x * 128;
    if (causal && colBase > rowBase + 127) return;   // fully-masked tile

    __shared__ float As[16][132];
    __shared__ float Bs[16][132];

    const int tid = threadIdx.x;
    const int tx = tid & 15, ty = tid >> 4;

    ull acc[8][4];
#pragma unroll
    for (int i = 0; i < 8; i++)
#pragma unroll
        for (int j = 0; j < 4; j++) acc[i][j] = 0ull;

    for (int k0 = 0; k0 < K; k0 += 16) {
#pragma unroll
        for (int i = 0; i < 2; i++) {
            int j  = tid + i * 256;         // float4 id, 512 per tile
            int r  = j >> 2;                // 0..127
            int c4 = j & 3;                 // 0..3
            float4 av = *reinterpret_cast<const float4*>(
                A + (size_t)(rowBase + r) * lda + k0 + c4 * 4);
            As[c4*4+0][r] = av.x; As[c4*4+1][r] = av.y;
            As[c4*4+2][r] = av.z; As[c4*4+3][r] = av.w;
            float4 bv = *reinterpret_cast<const float4*>(
                B + (size_t)(colBase + r) * ldb + k0 + c4 * 4);
            Bs[c4*4+0][r] = bv.x; Bs[c4*4+1][r] = bv.y;
            Bs[c4*4+2][r] = bv.z; Bs[c4*4+3][r] = bv.w;
        }
        __syncthreads();
#pragma unroll
        for (int kk = 0; kk < 16; kk++) {
            float4 a0 = *reinterpret_cast<const float4*>(&As[kk][ty * 8]);
            float4 a1 = *reinterpret_cast<const float4*>(&As[kk][ty * 8 + 4]);
            const ull* bp = reinterpret_cast<const ull*>(&Bs[kk][tx * 8]);
            ull b0 = bp[0], b1 = bp[1], b2 = bp[2], b3 = bp[3];
            ull ad[8];
            ad[0] = dup2(a0.x); ad[1] = dup2(a0.y); ad[2] = dup2(a0.z); ad[3] = dup2(a0.w);
            ad[4] = dup2(a1.x); ad[5] = dup2(a1.y); ad[6] = dup2(a1.z); ad[7] = dup2(a1.w);
#pragma unroll
            for (int i = 0; i < 8; i++) {
                fma2(acc[i][0], ad[i], b0);
                fma2(acc[i][1], ad[i], b1);
                fma2(acc[i][2], ad[i], b2);
                fma2(acc[i][3], ad[i], b3);
            }
        }
        __syncthreads();
    }

#pragma unroll
    for (int i = 0; i < 8; i++) {
        float* crow = C + (size_t)(rowBase + ty * 8 + i) * ldc + colBase + tx * 8;
        float2 p0 = unpk(acc[i][0]), p1 = unpk(acc[i][1]);
        float2 p2 = unpk(acc[i][2]), p3 = unpk(acc[i][3]);
        float4 o0 = make_float4(p0.x * scale, p0.y * scale, p1.x * scale, p1.y * scale);
        float4 o1 = make_float4(p2.x * scale, p2.y * scale, p3.x * scale, p3.y * scale);
        *reinterpret_cast<float4*>(crow)     = o0;
        *reinterpret_cast<float4*>(crow + 4) = o1;
    }
}

// =================================================================================
// NN GEMM: C[m,n] = scale * sum_k A[m,k] * B[k,n]   (B is K-major rows, n contiguous)
// Used for attn @ v.
// =================================================================================
__global__ void __launch_bounds__(256, 2) gemm_nn_kernel(
    const float* __restrict__ A, const float* __restrict__ B, float* __restrict__ C,
    int K, int lda, int ldb, int ldc,
    long long aSb, long long aSh, long long bSb, long long bSh,
    long long cSb, long long cSh, int nInner, float scale)
{
    int z  = blockIdx.z;
    int bb = z / nInner, hh = z - bb * nInner;
    A += bb * aSb + hh * aSh;
    B += bb * bSb + hh * bSh;
    C += bb * cSb + hh * cSh;

    const int rowBase = blockIdx.y * 128;
    const int colBase = blockIdx.x * 128;

    __shared__ float As[16][132];
    __shared__ float Bs[16][132];

    const int tid = threadIdx.x;
    const int tx = tid & 15, ty = tid >> 4;

    ull acc[8][4];
#pragma unroll
    for (int i = 0; i < 8; i++)
#pragma unroll
        for (int j = 0; j < 4; j++) acc[i][j] = 0ull;

    for (int k0 = 0; k0 < K; k0 += 16) {
#pragma unroll
        for (int i = 0; i < 2; i++) {
            int j  = tid + i * 256;
            {   // A tile (K-contiguous rows) -> transposed into As[k][m]
                int r = j >> 2, c4 = j & 3;
                float4 av = *reinterpret_cast<const float4*>(
                    A + (size_t)(rowBase + r) * lda + k0 + c4 * 4);
                As[c4*4+0][r] = av.x; As[c4*4+1][r] = av.y;
                As[c4*4+2][r] = av.z; As[c4*4+3][r] = av.w;
            }
            {   // B tile [BK][BN], rows are k, n contiguous -> direct copy
                int r = j >> 5, c4 = j & 31;
                float4 bv = *reinterpret_cast<const float4*>(
                    B + (size_t)(k0 + r) * ldb + colBase + c4 * 4);
                *reinterpret_cast<float4*>(&Bs[r][c4 * 4]) = bv;
            }
        }
        __syncthreads();
#pragma unroll
        for (int kk = 0; kk < 16; kk++) {
            float4 a0 = *reinterpret_cast<const float4*>(&As[kk][ty * 8]);
            float4 a1 = *reinterpret_cast<const float4*>(&As[kk][ty * 8 + 4]);
            const ull* bp = reinterpret_cast<const ull*>(&Bs[kk][tx * 8]);
            ull b0 = bp[0], b1 = bp[1], b2 = bp[2], b3 = bp[3];
            ull ad[8];
            ad[0] = dup2(a0.x); ad[1] = dup2(a0.y); ad[2] = dup2(a0.z); ad[3] = dup2(a0.w);
            ad[4] = dup2(a1.x); ad[5] = dup2(a1.y); ad[6] = dup2(a1.z); ad[7] = dup2(a1.w);
#pragma unroll
            for (int i = 0; i < 8; i++) {
                fma2(acc[i][0], ad[i], b0);
                fma2(acc[i][1], ad[i], b1);
                fma2(acc[i][2], ad[i], b2);
                fma2(acc[i][3], ad[i], b3);
            }
        }
        __syncthreads();
    }

#pragma unroll
    for (int i = 0; i < 8; i++) {
        float* crow = C + (size_t)(rowBase + ty * 8 + i) * ldc + colBase + tx * 8;
        float2 p0 = unpk(acc[i][0]), p1 = unpk(acc[i][1]);
        float2 p2 = unpk(acc[i][2]), p3 = unpk(acc[i][3]);
        float4 o0 = make_float4(p0.x * scale, p0.y * scale, p1.x * scale, p1.y * scale);
        float4 o1 = make_float4(p2.x * scale, p2.y * scale, p3.x * scale, p3.y * scale);
        *reinterpret_cast<float4*>(crow)     = o0;
        *reinterpret_cast<float4*>(crow + 4) = o1;
    }
}

// =================================================================================
// bmean[s] = 0.1 * mean_k bias[s,k]
// =================================================================================
__global__ void bmean_kernel(const float* __restrict__ bias, float* __restrict__ bm)
{
    __shared__ float red[256];
    int r = blockIdx.x;
    const float* row = bias + (size_t)r * SQ;
    float s = 0.f;
    for (int i = threadIdx.x; i < SQ; i += 256) s += row[i];
    red[threadIdx.x] = s; __syncthreads();
    for (int off = 128; off; off >>= 1) {
        if (threadIdx.x < off) red[threadIdx.x] += red[threadIdx.x + off];
        __syncthreads();
    }
    if (threadIdx.x == 0) bm[r] = red[0] * (0.1f / 2048.0f);
}

// =================================================================================
// In-place RoPE on q and k + add bmean. One thread per (m, h, d2) pair, d2 in [0,64).
// =================================================================================
__global__ void rope_kernel(float* __restrict__ q, float* __restrict__ k,
                            const float* __restrict__ bm)
{
    int idx = blockIdx.x * 256 + threadIdx.x;      // < 4096*16*64 = 4194304
    int d2 = idx & 63;
    int h  = (idx >> 6) & 15;
    int m  = idx >> 10;                            // 0..4095  (b*S + s)
    int s  = m & (SQ - 1);

    float invf = (float)exp(-((double)(2 * d2) / 128.0) * log(10000.0));
    float ang  = (float)s * invf;                  // fp32 multiply like the reference
    float sn, cs;
    sincosf(ang, &sn, &cs);
    float b = bm[s];

    size_t off = (size_t)m * HID + (size_t)h * HDIM + d2;
    float q0 = q[off], q1 = q[off + 64];
    q[off]      = q0 * cs - q1 * sn + b;
    q[off + 64] = q1 * cs + q0 * sn + b;
    float k0 = k[off], k1 = k[off + 64];
    k[off]      = k0 * cs - k1 * sn + b;
    k[off + 64] = k1 * cs + k0 * sn + b;
}

// =================================================================================
// Row softmax with bias add + causal mask, in-place on the scores buffer.
// One block per (z, q) row. Only k<=q are live; k>q written as 0.
// =================================================================================
__global__ void softmax_kernel(float* __restrict__ attn, const float* __restrict__ bias)
{
    __shared__ float buf[2048];
    __shared__ float red[256];
    int qrow = blockIdx.x;
    long long base = (long long)blockIdx.y * SQ * SQ + (long long)qrow * SQ;
    float* row = attn + base;
    const float* brow = bias + (size_t)qrow * SQ;
    int L = qrow + 1;
    int tid = threadIdx.x;

    float mx = -3.402823466e38f;
    for (int i = tid; i < L; i += 256) {
        float v = row[i] + brow[i];
        buf[i] = v;
        mx = fmaxf(mx, v);
    }
    red[tid] = mx; __syncthreads();
    for (int off = 128; off; off >>= 1) {
        if (tid < off) red[tid] = fmaxf(red[tid], red[tid + off]);
        __syncthreads();
    }
    mx = red[0]; __syncthreads();

    float sum = 0.f;
    for (int i = tid; i < L; i += 256) {
        float e = __expf(buf[i] - mx);
        buf[i] = e;
        sum += e;
    }
    red[tid] = sum; __syncthreads();
    for (int off = 128; off; off >>= 1) {
        if (tid < off) red[tid] += red[tid + off];
        __syncthreads();
    }
    float inv = 1.0f / red[0];

    for (int i = tid; i < L; i += 256)       row[i] = buf[i] * inv;
    for (int i = L + tid; i < SQ; i += 256)  row[i] = 0.f;
}

// =================================================================================
// Host launcher
// =================================================================================
extern "C" void kernel_launch(void* const* d_in, const int* in_sizes, int n_in,
                              void* d_out, int out_size)
{
    const float* x    = (const float*)d_in[0];
    const float* Wq   = (const float*)d_in[1];
    const float* Wk   = (const float*)d_in[2];
    const float* Wv   = (const float*)d_in[3];
    const float* Wo   = (const float*)d_in[4];
    const float* bias = (const float*)d_in[5];
    float* out = (float*)d_out;

    float *pq, *pk, *pv, *pao, *pbm, *pattn;
    cudaGetSymbolAddress((void**)&pq,    g_q);
    cudaGetSymbolAddress((void**)&pk,    g_k);
    cudaGetSymbolAddress((void**)&pv,    g_v);
    cudaGetSymbolAddress((void**)&pao,   g_ao);
    cudaGetSymbolAddress((void**)&pbm,   g_bm);
    cudaGetSymbolAddress((void**)&pattn, g_attn);

    const long long OUT_N = 8388608LL;       // 2*2048*2048
    const long long ATT_N = 134217728LL;     // 2*16*2048*2048
    float* outPtr  = out;
    float* attnPtr;
    long long osz = (long long)out_size;
    if (osz >= OUT_N + ATT_N)      { attnPtr = out + OUT_N; }           // (output, attn)
    else if (osz == ATT_N)         { attnPtr = out; outPtr = pq; }      // attn only
    else                           { attnPtr = pattn; }                 // output only

    const long long SH = (long long)SQ * HID;   // 4194304
    const long long SS = (long long)SQ * SQ;    // 4194304

    // 1) per-row bias mean
    bmean_kernel<<<SQ, 256>>>(bias, pbm);

    // 2) QKV projections: y = x @ W^T   (M=4096, N=2048, K=2048)
    dim3 gProj(16, 32, 1);
    gemm_nt_kernel<<<gProj, 256>>>(x, Wq, pq, 2048, 2048, 2048, 2048,
                                   0, 0, 0, 0, 0, 0, 1, 1.0f, 0);
    gemm_nt_kernel<<<gProj, 256>>>(x, Wk, pk, 2048, 2048, 2048, 2048,
                                   0, 0, 0, 0, 0, 0, 1, 1.0f, 0);
    gemm_nt_kernel<<<gProj, 256>>>(x, Wv, pv, 2048, 2048, 2048, 2048,
                                   0, 0, 0, 0, 0, 0, 1, 1.0f, 0);

    // 3) RoPE + bmean on q, k (in place)
    rope_kernel<<<16384, 256>>>(pq, pk, pbm);

    // 4) scores = q.k^T / sqrt(D)   batched over z = b*16+h, causal tile-skip
    dim3 gScore(16, 16, 32);
    gemm_nt_kernel<<<gScore, 256>>>(pq, pk, attnPtr, 128, 2048, 2048, 2048,
                                    SH, 128, SH, 128,
                                    (long long)NHEAD * SS, SS,
                                    NHEAD, 0.08838834764831845f, 1);

    // 5) bias add + causal softmax (in place)
    softmax_kernel<<<dim3(SQ, 32), 256>>>(attnPtr, bias);

    // 6) attn @ v   (M=2048, N=128, K=2048) batched
    dim3 gAV(1, 16, 32);
    gemm_nn_kernel<<<gAV, 256>>>(attnPtr, pv, pao, 2048, 2048, 2048, 2048,
                                 (long long)NHEAD * SS, SS,
                                 SH, 128,
                                 SH, 128,
                                 NHEAD, 1.0f);

    // 7) output = attn_out @ Wo^T
    gemm_nt_kernel<<<gProj, 256>>>(pao, Wo, outPtr, 2048, 2048, 2048, 2048,
                                   0, 0, 0, 0, 0, 0, 1, 1.0f, 0);
}

// round 8
// speedup vs baseline: 1.8785x; 1.8785x over previous
#include <cuda_runtime.h>
#include <cuda_bf16.h>
#include <math.h>
#include <stdint.h>

#define SQ   2048
#define HID  2048
#define MR   4096

typedef __nv_bfloat16  bf16;
typedef __nv_bfloat162 bf162;

// ----------------------------- static scratch ------------------------------
__device__ float g_q [MR * HID];
__device__ float g_k [MR * HID];
__device__ float g_v [MR * HID];
__device__ float g_ao[MR * HID];
__device__ float g_bm[SQ];
__device__ float g_attn[134217728];

__device__ bf16 g_xh [MR * HID],  g_xl [MR * HID];
__device__ bf16 g_wqh[HID * HID], g_wql[HID * HID];
__device__ bf16 g_wkh[HID * HID], g_wkl[HID * HID];
__device__ bf16 g_wvh[HID * HID], g_wvl[HID * HID];
__device__ bf16 g_woh[HID * HID], g_wol[HID * HID];
__device__ bf16 g_qh [MR * HID],  g_ql [MR * HID];
__device__ bf16 g_kh [MR * HID],  g_kl [MR * HID];
__device__ bf16 g_vth[MR * HID],  g_vtl[MR * HID];
__device__ bf16 g_aoh[MR * HID],  g_aol[MR * HID];
__device__ bf16 g_ah [134217728], g_al [134217728];

// ----------------------------- helpers -------------------------------------
__device__ __forceinline__ uint32_t smem_u32(const void* p) {
    uint32_t a;
    asm("{ .reg .u64 t; cvta.to.shared.u64 t, %1; cvt.u32.u64 %0, t; }" : "=r"(a) : "l"(p));
    return a;
}
__device__ __forceinline__ void cp16(uint32_t dst, const void* src) {
    asm volatile("cp.async.cg.shared.global [%0], [%1], 16;" :: "r"(dst), "l"(src));
}
#define CP_COMMIT() asm volatile("cp.async.commit_group;" ::: "memory")
#define CP_WAIT(n)  asm volatile("cp.async.wait_group %0;" :: "n"(n) : "memory")

#define LDSM4(r0, r1, r2, r3, addr) \
    asm volatile("ldmatrix.sync.aligned.m8n8.x4.shared.b16 {%0,%1,%2,%3}, [%4];" \
        : "=r"(r0), "=r"(r1), "=r"(r2), "=r"(r3) : "r"(addr))

__device__ __forceinline__ void mma_bf16(float* c,
    uint32_t a0, uint32_t a1, uint32_t a2, uint32_t a3, uint32_t b0, uint32_t b1)
{
    asm volatile(
        "mma.sync.aligned.m16n8k16.row.col.f32.bf16.bf16.f32 "
        "{%0,%1,%2,%3}, {%4,%5,%6,%7}, {%8,%9}, {%0,%1,%2,%3};"
        : "+f"(c[0]), "+f"(c[1]), "+f"(c[2]), "+f"(c[3])
        : "r"(a0), "r"(a1), "r"(a2), "r"(a3), "r"(b0), "r"(b1));
}

// =================================================================================
// Split-bf16 NT GEMM via mma.sync: C[m,n] = scale * sum_k (Ah+Al)[m,k]*(Bh+Bl)[n,k]
// (lo*lo dropped). CTA 128x128, 8 warps (2x4) of 64x32, BK=32, double-buffered
// cp.async. Smem per stage: Ah,Al,Bh,Bl each [128][40] bf16 (pad 8) = 40960 B.
// mode&1: causal tile skip. mode&2: Keff = rowBase+128 (causal attn@v).
// =================================================================================
#define STG_BYTES 40960u
#define ARR_BYTES 10240u   // 128*40*2

__device__ __forceinline__ void load_stage32(
    uint32_t sbase, int slot, int k0,
    const bf16* __restrict__ Ah, const bf16* __restrict__ Al,
    const bf16* __restrict__ Bh, const bf16* __restrict__ Bl,
    int lda, int ldb, int rowBase, int colBase, int tid)
{
    uint32_t base = sbase + (uint32_t)slot * STG_BYTES;
    int r  = tid >> 1;
    int c0 = (tid & 1) << 1;
#pragma unroll
    for (int i = 0; i < 2; i++) {
        int c = c0 + i;                                   // 8-bf16 chunk 0..3
        uint32_t off = (uint32_t)(r * 40 + c * 8) * 2;
        const size_t ga = (size_t)(rowBase + r) * lda + k0 + c * 8;
        const size_t gb = (size_t)(colBase + r) * ldb + k0 + c * 8;
        cp16(base +                off, Ah + ga);
        cp16(base + ARR_BYTES    + off, Al + ga);
        cp16(base + 2u*ARR_BYTES + off, Bh + gb);
        cp16(base + 3u*ARR_BYTES + off, Bl + gb);
    }
    CP_COMMIT();
}

__global__ void __launch_bounds__(256, 1)
mma_gemm(const bf16* __restrict__ Ahi, const bf16* __restrict__ Alo,
         const bf16* __restrict__ Bhi, const bf16* __restrict__ Blo,
         float* __restrict__ C,
         int K, int lda, int ldb, int ldc,
         long long aSb, long long aSh, long long bSb, long long bSh,
         long long cSb, long long cSh, int nInner, float scale, int mode)
{
    extern __shared__ char smem[];
    const int z  = blockIdx.z;
    const int bb = z / nInner, hh = z - bb * nInner;
    const bf16* Ah = Ahi + bb * aSb + hh * aSh;
    const bf16* Al = Alo + bb * aSb + hh * aSh;
    const bf16* Bh = Bhi + bb * bSb + hh * bSh;
    const bf16* Bl = Blo + bb * bSb + hh * bSh;
    float* Cz = C + bb * cSb + hh * cSh;

    const int rowBase = blockIdx.y * 128;
    const int colBase = blockIdx.x * 128;
    if ((mode & 1) && colBase > rowBase + 127) return;
    int Keff = K;
    if (mode & 2) { int kl = rowBase + 128; Keff = kl < K ? kl : K; }
    const int nst = Keff >> 5;

    const uint32_t sb = smem_u32(smem);
    const int tid = threadIdx.x, lane = tid & 31, wid = tid >> 5;
    const int warpM = (wid & 1) << 6;      // 0 or 64
    const int warpN = (wid >> 1) << 5;     // 0,32,64,96

    // ldmatrix per-lane smem offsets (bytes), relative to array base
    const uint32_t offA = (uint32_t)((warpM + (lane & 15)) * 40
                                     + ((lane >> 4) << 3)) * 2;
    const uint32_t offB = (uint32_t)((warpN + (lane & 7) + ((lane >> 4) << 3)) * 40
                                     + (((lane >> 3) & 1) << 3)) * 2;

    float acc[4][4][4];
#pragma unroll
    for (int i = 0; i < 4; i++)
#pragma unroll
        for (int j = 0; j < 4; j++)
#pragma unroll
            for (int t = 0; t < 4; t++) acc[i][j][t] = 0.f;

    load_stage32(sb, 0, 0, Ah, Al, Bh, Bl, lda, ldb, rowBase, colBase, tid);

    for (int j = 0; j < nst; j++) {
        if (j + 1 < nst) {
            load_stage32(sb, (j + 1) & 1, (j + 1) * 32, Ah, Al, Bh, Bl,
                         lda, ldb, rowBase, colBase, tid);
            CP_WAIT(1);
        } else {
            CP_WAIT(0);
        }
        __syncthreads();

        const uint32_t base = sb + (uint32_t)(j & 1) * STG_BYTES;
#pragma unroll
        for (int ks = 0; ks < 32; ks += 16) {
            uint32_t ah[4][4], al[4][4], bh[2][4], bl[2][4];
#pragma unroll
            for (int t = 0; t < 4; t++) {
                uint32_t ad = base + offA + (uint32_t)((t * 640 + ks) * 2);
                LDSM4(ah[t][0], ah[t][1], ah[t][2], ah[t][3], ad);
                LDSM4(al[t][0], al[t][1], al[t][2], al[t][3], ad + ARR_BYTES);
            }
#pragma unroll
            for (int g = 0; g < 2; g++) {
                uint32_t bd = base + 2u*ARR_BYTES + offB + (uint32_t)((g * 640 + ks) * 2);
                LDSM4(bh[g][0], bh[g][1], bh[g][2], bh[g][3], bd);
                LDSM4(bl[g][0], bl[g][1], bl[g][2], bl[g][3], bd + ARR_BYTES);
            }
#pragma unroll
            for (int mt = 0; mt < 4; mt++) {
#pragma unroll
                for (int g = 0; g < 2; g++) {
                    // hi*hi
                    mma_bf16(acc[mt][2*g],   ah[mt][0], ah[mt][1], ah[mt][2], ah[mt][3], bh[g][0], bh[g][1]);
                    mma_bf16(acc[mt][2*g+1], ah[mt][0], ah[mt][1], ah[mt][2], ah[mt][3], bh[g][2], bh[g][3]);
                    // hi*lo
                    mma_bf16(acc[mt][2*g],   ah[mt][0], ah[mt][1], ah[mt][2], ah[mt][3], bl[g][0], bl[g][1]);
                    mma_bf16(acc[mt][2*g+1], ah[mt][0], ah[mt][1], ah[mt][2], ah[mt][3], bl[g][2], bl[g][3]);
                    // lo*hi
                    mma_bf16(acc[mt][2*g],   al[mt][0], al[mt][1], al[mt][2], al[mt][3], bh[g][0], bh[g][1]);
                    mma_bf16(acc[mt][2*g+1], al[mt][0], al[mt][1], al[mt][2], al[mt][3], bh[g][2], bh[g][3]);
                }
            }
        }
        __syncthreads();
    }

    // epilogue: m16n8 C fragment -> float2 stores
    const int row0 = rowBase + warpM + (lane >> 2);
    const int col0 = colBase + warpN + (lane & 3) * 2;
#pragma unroll
    for (int mt = 0; mt < 4; mt++) {
#pragma unroll
        for (int nt = 0; nt < 4; nt++) {
            float2 v0 = make_float2(acc[mt][nt][0] * scale, acc[mt][nt][1] * scale);
            float2 v1 = make_float2(acc[mt][nt][2] * scale, acc[mt][nt][3] * scale);
            size_t r0 = (size_t)(row0 + mt * 16) * ldc + col0 + nt * 8;
            *reinterpret_cast<float2*>(Cz + r0)                 = v0;
            *reinterpret_cast<float2*>(Cz + r0 + 8 * (size_t)ldc) = v1;
        }
    }
}

// =================================================================================
// Elementwise kernels
// =================================================================================
__device__ __forceinline__ void sp(float v, bf16& h, bf16& l) {
    h = __float2bfloat16_rn(v);
    l = __float2bfloat16_rn(v - __bfloat162float(h));
}

__global__ void split_kernel(const float* __restrict__ in,
                             bf16* __restrict__ hi, bf16* __restrict__ lo, int n4)
{
    int i = blockIdx.x * 256 + threadIdx.x;
    if (i >= n4) return;
    float4 v = reinterpret_cast<const float4*>(in)[i];
    bf16 h0, l0, h1, l1, h2, l2, h3, l3;
    sp(v.x, h0, l0); sp(v.y, h1, l1); sp(v.z, h2, l2); sp(v.w, h3, l3);
    bf162 a, b;
    a.x = h0; a.y = h1; b.x = h2; b.y = h3;
    reinterpret_cast<bf162*>(hi)[i * 2] = a; reinterpret_cast<bf162*>(hi)[i * 2 + 1] = b;
    a.x = l0; a.y = l1; b.x = l2; b.y = l3;
    reinterpret_cast<bf162*>(lo)[i * 2] = a; reinterpret_cast<bf162*>(lo)[i * 2 + 1] = b;
}

__global__ void bmean_kernel(const float* __restrict__ bias, float* __restrict__ bm)
{
    __shared__ float red[256];
    int r = blockIdx.x;
    const float* row = bias + (size_t)r * SQ;
    float s = 0.f;
    for (int i = threadIdx.x; i < SQ; i += 256) s += row[i];
    red[threadIdx.x] = s; __syncthreads();
    for (int o = 128; o; o >>= 1) {
        if (threadIdx.x < o) red[threadIdx.x] += red[threadIdx.x + o];
        __syncthreads();
    }
    if (threadIdx.x == 0) bm[r] = red[0] * (0.1f / 2048.0f);
}

__global__ void rope_split_kernel(const float* __restrict__ q, const float* __restrict__ k,
                                  const float* __restrict__ bm,
                                  bf16* __restrict__ qh, bf16* __restrict__ ql,
                                  bf16* __restrict__ kh, bf16* __restrict__ kl)
{
    int idx = blockIdx.x * 256 + threadIdx.x;
    int d2 = idx & 63;
    int h  = (idx >> 6) & 15;
    int m  = idx >> 10;
    int s  = m & (SQ - 1);

    float invf = (float)exp(-((double)(2 * d2) / 128.0) * log(10000.0));
    float sn, cs;
    sincosf((float)s * invf, &sn, &cs);
    float b = bm[s];

    size_t off = (size_t)m * HID + (size_t)h * 128 + d2;
    float q0 = q[off], q1 = q[off + 64];
    float k0 = k[off], k1 = k[off + 64];
    float qa = q0 * cs - q1 * sn + b;
    float qb = q1 * cs + q0 * sn + b;
    float ka = k0 * cs - k1 * sn + b;
    float kb = k1 * cs + k0 * sn + b;
    bf16 h_, l_;
    sp(qa, h_, l_); qh[off]      = h_; ql[off]      = l_;
    sp(qb, h_, l_); qh[off + 64] = h_; ql[off + 64] = l_;
    sp(ka, h_, l_); kh[off]      = h_; kl[off]      = l_;
    sp(kb, h_, l_); kh[off + 64] = h_; kl[off + 64] = l_;
}

__global__ void vsplit_kernel(const float* __restrict__ v,
                              bf16* __restrict__ vth, bf16* __restrict__ vtl)
{
    __shared__ float t[32][33];
    int z = blockIdx.z, b = z >> 4, h = z & 15;
    int s0 = blockIdx.x * 32, d0 = blockIdx.y * 32;
    int tx = threadIdx.x, ty = threadIdx.y;
#pragma unroll
    for (int i = 0; i < 4; i++) {
        int sl = ty * 4 + i;
        t[sl][tx] = v[(size_t)(b * SQ + s0 + sl) * HID + h * 128 + d0 + tx];
    }
    __syncthreads();
#pragma unroll
    for (int i = 0; i < 4; i++) {
        int dl = ty * 4 + i;
        float x = t[tx][dl];
        bf16 hi, lo; sp(x, hi, lo);
        size_t o = ((size_t)z * 128 + d0 + dl) * SQ + s0 + tx;
        vth[o] = hi; vtl[o] = lo;
    }
}

__global__ void softmax_kernel(float* __restrict__ attn, const float* __restrict__ bias,
                               bf16* __restrict__ ah, bf16* __restrict__ al)
{
    __shared__ float buf[2048];
    __shared__ float red[256];
    int qrow = blockIdx.x;
    long long base = (long long)blockIdx.y * SQ * SQ + (long long)qrow * SQ;
    float* row = attn + base;
    const float* brow = bias + (size_t)qrow * SQ;
    int L = qrow + 1;
    int tileEnd = ((qrow >> 7) + 1) << 7;
    int tid = threadIdx.x;

    float mx = -3.402823466e38f;
    for (int i = tid; i < L; i += 256) {
        float vv = row[i] + brow[i];
        buf[i] = vv;
        mx = fmaxf(mx, vv);
    }
    red[tid] = mx; __syncthreads();
    for (int o = 128; o; o >>= 1) {
        if (tid < o) red[tid] = fmaxf(red[tid], red[tid + o]);
        __syncthreads();
    }
    mx = red[0]; __syncthreads();

    float sum = 0.f;
    for (int i = tid; i < L; i += 256) {
        float e = __expf(buf[i] - mx);
        buf[i] = e;
        sum += e;
    }
    red[tid] = sum; __syncthreads();
    for (int o = 128; o; o >>= 1) {
        if (tid < o) red[tid] += red[tid + o];
        __syncthreads();
    }
    float inv = 1.0f / red[0];

    for (int i = tid; i < L; i += 256) {
        float a = buf[i] * inv;
        row[i] = a;
        bf16 hi, lo; sp(a, hi, lo);
        ah[base + i] = hi; al[base + i] = lo;
    }
    bf16 z16 = __float2bfloat16_rn(0.f);
    for (int i = L + tid; i < tileEnd; i += 256) { ah[base + i] = z16; al[base + i] = z16; }
    for (int i = L + tid; i < SQ; i += 256)       row[i] = 0.f;
}

// =================================================================================
// Host launcher
// =================================================================================
extern "C" void kernel_launch(void* const* d_in, const int* in_sizes, int n_in,
                              void* d_out, int out_size)
{
    const float* x    = (const float*)d_in[0];
    const float* Wq   = (const float*)d_in[1];
    const float* Wk   = (const float*)d_in[2];
    const float* Wv   = (const float*)d_in[3];
    const float* Wo   = (const float*)d_in[4];
    const float* bias = (const float*)d_in[5];
    float* out = (float*)d_out;

    float *pq, *pk, *pv, *pao, *pbm, *pattn;
    bf16 *pxh, *pxl, *pwqh, *pwql, *pwkh, *pwkl, *pwvh, *pwvl, *pwoh, *pwol;
    bf16 *pqh, *pql, *pkh, *pkl, *pvth, *pvtl, *paoh, *paol, *pah, *pal;
    cudaGetSymbolAddress((void**)&pq, g_q);     cudaGetSymbolAddress((void**)&pk, g_k);
    cudaGetSymbolAddress((void**)&pv, g_v);     cudaGetSymbolAddress((void**)&pao, g_ao);
    cudaGetSymbolAddress((void**)&pbm, g_bm);   cudaGetSymbolAddress((void**)&pattn, g_attn);
    cudaGetSymbolAddress((void**)&pxh, g_xh);   cudaGetSymbolAddress((void**)&pxl, g_xl);
    cudaGetSymbolAddress((void**)&pwqh, g_wqh); cudaGetSymbolAddress((void**)&pwql, g_wql);
    cudaGetSymbolAddress((void**)&pwkh, g_wkh); cudaGetSymbolAddress((void**)&pwkl, g_wkl);
    cudaGetSymbolAddress((void**)&pwvh, g_wvh); cudaGetSymbolAddress((void**)&pwvl, g_wvl);
    cudaGetSymbolAddress((void**)&pwoh, g_woh); cudaGetSymbolAddress((void**)&pwol, g_wol);
    cudaGetSymbolAddress((void**)&pqh, g_qh);   cudaGetSymbolAddress((void**)&pql, g_ql);
    cudaGetSymbolAddress((void**)&pkh, g_kh);   cudaGetSymbolAddress((void**)&pkl, g_kl);
    cudaGetSymbolAddress((void**)&pvth, g_vth); cudaGetSymbolAddress((void**)&pvtl, g_vtl);
    cudaGetSymbolAddress((void**)&paoh, g_aoh); cudaGetSymbolAddress((void**)&paol, g_aol);
    cudaGetSymbolAddress((void**)&pah, g_ah);   cudaGetSymbolAddress((void**)&pal, g_al);

    const long long OUT_N = 8388608LL, ATT_N = 134217728LL;
    float* outPtr = out;
    float* attnPtr;
    long long osz = (long long)out_size;
    if (osz >= OUT_N + ATT_N) { attnPtr = out + OUT_N; }
    else if (osz == ATT_N)    { attnPtr = out; outPtr = pq; }
    else                      { attnPtr = pattn; }

    const long long SH = (long long)SQ * HID;
    const long long SS = (long long)SQ * SQ;
    const int SMEM = 2 * 40960;
    cudaFuncSetAttribute(mma_gemm, cudaFuncAttributeMaxDynamicSharedMemorySize, SMEM);

    bmean_kernel<<<SQ, 256>>>(bias, pbm);
    split_kernel<<<8192, 256>>>(x,  pxh,  pxl,  2097152);
    split_kernel<<<4096, 256>>>(Wq, pwqh, pwql, 1048576);
    split_kernel<<<4096, 256>>>(Wk, pwkh, pwkl, 1048576);
    split_kernel<<<4096, 256>>>(Wv, pwvh, pwvl, 1048576);
    split_kernel<<<4096, 256>>>(Wo, pwoh, pwol, 1048576);

    // QKV projections (M=4096, N=2048, K=2048): y = x @ W^T
    dim3 gProj(16, 32, 1);
    mma_gemm<<<gProj, 256, SMEM>>>(pxh, pxl, pwqh, pwql, pq, 2048, 2048, 2048, 2048,
                                   0, 0, 0, 0, 0, 0, 1, 1.0f, 0);
    mma_gemm<<<gProj, 256, SMEM>>>(pxh, pxl, pwkh, pwkl, pk, 2048, 2048, 2048, 2048,
                                   0, 0, 0, 0, 0, 0, 1, 1.0f, 0);
    mma_gemm<<<gProj, 256, SMEM>>>(pxh, pxl, pwvh, pwvl, pv, 2048, 2048, 2048, 2048,
                                   0, 0, 0, 0, 0, 0, 1, 1.0f, 0);

    rope_split_kernel<<<16384, 256>>>(pq, pk, pbm, pqh, pql, pkh, pkl);
    vsplit_kernel<<<dim3(64, 4, 32), dim3(32, 8)>>>(pv, pvth, pvtl);

    // scores = q.k^T / sqrt(128), causal tile-skip (K=128 per head)
    dim3 gScore(16, 16, 32);
    mma_gemm<<<gScore, 256, SMEM>>>(pqh, pql, pkh, pkl, attnPtr, 128, 2048, 2048, 2048,
                                    SH, 128, SH, 128,
                                    16 * SS, SS, 16, 0.08838834764831845f, 1);

    softmax_kernel<<<dim3(SQ, 32), 256>>>(attnPtr, bias, pah, pal);

    // attn @ v : A = attn bf16 [z][2048][2048], B = vT bf16 [z][128][2048], K-limited
    dim3 gAV(1, 16, 32);
    mma_gemm<<<gAV, 256, SMEM>>>(pah, pal, pvth, pvtl, pao, 2048, 2048, 2048, 2048,
                                 16 * SS, SS, SH, (long long)128 * SQ,
                                 SH, 128, 16, 1.0f, 2);

    split_kernel<<<8192, 256>>>(pao, paoh, paol, 2097152);

    // output = attn_out @ Wo^T
    mma_gemm<<<gProj, 256, SMEM>>>(paoh, paol, pwoh, pwol, outPtr, 2048, 2048, 2048, 2048,
                                   0, 0, 0, 0, 0, 0, 1, 1.0f, 0);
}